// round 16
// baseline (speedup 1.0000x reference)
#include <cuda_runtime.h>
#include <cuda_fp16.h>
#include <math.h>
#include <stdint.h>

#define BATCH 4
#define SEQ   2048
#define EMB   512
#define NH    8
#define DHD   64
#define BH    (BATCH*NH)

#define SMRH  72                // smem row stride in halves
#define LOG2E 1.4426950408889634f
#define SHIFT 8.0f              // fixed softmax shift (exp2 domain)

// Scratch (fp16). V stored transposed: [bh][dh][seq].
__device__ __align__(16) __half g_Q[BH * SEQ * DHD];
__device__ __align__(16) __half g_K[BH * SEQ * DHD];
__device__ __align__(16) __half g_V[BH * DHD * SEQ];
__device__ __align__(16) __half g_attn[BATCH * SEQ * EMB];
__device__ __align__(16) __half g_Wo_h[EMB * EMB];

// ---- helpers --------------------------------------------------------------
__device__ __forceinline__ uint32_t h2(float a, float b) {
    __half2 h = __floats2half2_rn(a, b);
    return *(uint32_t*)&h;
}
__device__ __forceinline__ uint32_t hex2(uint32_t x) {   // exp2 on packed fp16 pair
    uint32_t y;
    asm("ex2.approx.f16x2 %0, %1;" : "=r"(y) : "r"(x));
    return y;
}
__device__ __forceinline__ void mma_f16(float c[4],
                                        uint32_t a0, uint32_t a1, uint32_t a2, uint32_t a3,
                                        uint32_t b0, uint32_t b1) {
    asm volatile(
        "mma.sync.aligned.m16n8k16.row.col.f32.f16.f16.f32 "
        "{%0,%1,%2,%3}, {%4,%5,%6,%7}, {%8,%9}, {%0,%1,%2,%3};"
        : "+f"(c[0]), "+f"(c[1]), "+f"(c[2]), "+f"(c[3])
        : "r"(a0), "r"(a1), "r"(a2), "r"(a3), "r"(b0), "r"(b1));
}
__device__ __forceinline__ void ldm4(uint32_t& r0, uint32_t& r1, uint32_t& r2, uint32_t& r3,
                                     uint32_t addr) {
    asm volatile("ldmatrix.sync.aligned.m8n8.x4.shared.b16 {%0,%1,%2,%3}, [%4];"
                 : "=r"(r0), "=r"(r1), "=r"(r2), "=r"(r3) : "r"(addr));
}
__device__ __forceinline__ void ldm2(uint32_t& r0, uint32_t& r1, uint32_t addr) {
    asm volatile("ldmatrix.sync.aligned.m8n8.x2.shared.b16 {%0,%1}, [%2];"
                 : "=r"(r0), "=r"(r1) : "r"(addr));
}
__device__ __forceinline__ void cp16(uint32_t dst, const void* src) {
    asm volatile("cp.async.cg.shared.global [%0], [%1], 16;" :: "r"(dst), "l"(src));
}
__device__ __forceinline__ void cp_commit() { asm volatile("cp.async.commit_group;"); }
__device__ __forceinline__ void cp_wait1()  { asm volatile("cp.async.wait_group 1;" ::: "memory"); }

// ---------------------------------------------------------------------------
// Kernel 1: fused QKV projection + Wo fp32->fp16 conversion (proven, 20.6us).
// ---------------------------------------------------------------------------
#define QKV_BUFH (64*SMRH)
#define QKV_SMEM ((128*SMRH + 3*QKV_BUFH) * 2)
#define TSR 136                  // transpose-stage stride in halves

__global__ __launch_bounds__(256)
void qkv_conv_kernel(const float* __restrict__ x,
                     const float* __restrict__ Wq, const float* __restrict__ bq,
                     const float* __restrict__ Wk, const float* __restrict__ bk,
                     const float* __restrict__ Wv, const float* __restrict__ bv,
                     const float* __restrict__ Wo)
{
    if (blockIdx.x >= 512) {
        int idx = (blockIdx.x - 512) * 256 + threadIdx.x;
        float4 v = *(const float4*)(Wo + (size_t)idx * 4);
        uint2 o;
        o.x = h2(v.x, v.y);
        o.y = h2(v.z, v.w);
        *(uint2*)&g_Wo_h[(size_t)idx * 4] = o;
        return;
    }

    extern __shared__ __half smh[];
    __half* Xs = smh;                    // [128][SMRH]
    __half* Wsb = smh + 128 * SMRH;      // 3 x [64][SMRH]

    const int bid = blockIdx.x;
    const int st = bid & 15, b = (bid >> 4) & 3, h = bid >> 6;
    const int tid = threadIdx.x;
    const int wid = tid >> 5, lane = tid & 31;
    const int g = lane >> 2, tig = lane & 3;

    const float* xb = x + ((size_t)(b * SEQ + st * 128)) * EMB + h * DHD;
#pragma unroll
    for (int i = 0; i < 8; i++) {
        int idx = tid + i * 256;
        int r = idx >> 4, c4 = (idx & 15) << 2;
        float4 v = *(const float4*)(xb + (size_t)r * EMB + c4);
        uint2 o; o.x = h2(v.x, v.y); o.y = h2(v.z, v.w);
        *(uint2*)&Xs[r * SMRH + c4] = o;
    }
    const float* Wm[3] = {Wq, Wk, Wv};
#pragma unroll
    for (int m = 0; m < 3; m++) {
        const float* wsrc = Wm[m] + h * DHD * DHD;
        __half* Ws = Wsb + m * QKV_BUFH;
#pragma unroll
        for (int i = 0; i < 4; i++) {
            int idx = tid + i * 256;
            int r = idx >> 4, c4 = (idx & 15) << 2;
            float4 v = *(const float4*)(wsrc + r * DHD + c4);
            uint2 o; o.x = h2(v.x, v.y); o.y = h2(v.z, v.w);
            *(uint2*)&Ws[r * SMRH + c4] = o;
        }
    }
    __syncthreads();

    uint32_t xf[4][4];
    {
        const int r0 = wid * 16 + g;
#pragma unroll
        for (int kki = 0; kki < 4; kki++) {
            int kk = kki * 16;
            xf[kki][0] = *(const uint32_t*)&Xs[r0 * SMRH + kk + 2 * tig];
            xf[kki][1] = *(const uint32_t*)&Xs[(r0 + 8) * SMRH + kk + 2 * tig];
            xf[kki][2] = *(const uint32_t*)&Xs[r0 * SMRH + kk + 2 * tig + 8];
            xf[kki][3] = *(const uint32_t*)&Xs[(r0 + 8) * SMRH + kk + 2 * tig + 8];
        }
    }

    const float* bm[3] = {bq, bk, bv};
    const int bh = b * NH + h;
    const int row = wid * 16 + g;

#pragma unroll
    for (int m = 0; m < 3; m++) {
        const __half* Ws = Wsb + m * QKV_BUFH;
        float acc[8][4] = {};
#pragma unroll
        for (int kki = 0; kki < 4; kki++) {
            int kk = kki * 16;
#pragma unroll
            for (int nt = 0; nt < 8; nt++) {
                uint32_t b0 = *(const uint32_t*)&Ws[(nt * 8 + g) * SMRH + kk + 2 * tig];
                uint32_t b1 = *(const uint32_t*)&Ws[(nt * 8 + g) * SMRH + kk + 2 * tig + 8];
                mma_f16(acc[nt], xf[kki][0], xf[kki][1], xf[kki][2], xf[kki][3], b0, b1);
            }
        }
        const float* bb = bm[m] + h * DHD;
        if (m < 2) {
            const float scale = (m == 0) ? 0.125f * LOG2E : 1.0f;
            __half* op = ((m == 0) ? g_Q : g_K) + ((size_t)bh * SEQ + st * 128) * DHD;
#pragma unroll
            for (int nt = 0; nt < 8; nt++) {
                int col = nt * 8 + 2 * tig;
                float2 bias = *(const float2*)&bb[col];
                *(uint32_t*)&op[(size_t)row * DHD + col] =
                    h2((acc[nt][0] + bias.x) * scale, (acc[nt][1] + bias.y) * scale);
                *(uint32_t*)&op[(size_t)(row + 8) * DHD + col] =
                    h2((acc[nt][2] + bias.x) * scale, (acc[nt][3] + bias.y) * scale);
            }
        } else {
            // V: stage transpose [64 dh][128 seq] in smem, then coalesced uint4 STG
            __syncthreads();
            __half* Ts = smh;
#pragma unroll
            for (int nt = 0; nt < 8; nt++) {
                int col = nt * 8 + 2 * tig;
                float2 bias = *(const float2*)&bb[col];
                Ts[col * TSR + row]           = __float2half(acc[nt][0] + bias.x);
                Ts[(col + 1) * TSR + row]     = __float2half(acc[nt][1] + bias.y);
                Ts[col * TSR + row + 8]       = __float2half(acc[nt][2] + bias.x);
                Ts[(col + 1) * TSR + row + 8] = __float2half(acc[nt][3] + bias.y);
            }
            __syncthreads();
            __half* op = g_V + (size_t)bh * DHD * SEQ + st * 128;
#pragma unroll
            for (int i = 0; i < 4; i++) {
                int idx = tid + i * 256;
                int r = idx >> 4, c8 = (idx & 15) * 8;
                *(uint4*)(op + (size_t)r * SEQ + c8) = *(const uint4*)&Ts[r * TSR + c8];
            }
        }
    }
}

// ---------------------------------------------------------------------------
// Kernel 2: flash attention (round-14 proven best: 4 warps x 32 q-rows,
// ldmatrix B loads, fixed-shift softmax, ones-column, 3-stage ring).
// grid (SEQ/128, BH), 128 threads.
// ---------------------------------------------------------------------------
#define KSZ   (64*SMRH)
#define VSZ   (72*SMRH)
#define BUFSZ (KSZ+VSZ)
#define NBUF  3
#define ATTN_SMEM (NBUF*BUFSZ*2)

__global__ __launch_bounds__(128, 3)
void attn_kernel()
{
    extern __shared__ __half smh[];
    const uint32_t sm_u32 = (uint32_t)__cvta_generic_to_shared(smh);

    const int bh = blockIdx.y;
    const int q0 = blockIdx.x * 128;
    const int tid = threadIdx.x;
    const int wid = tid >> 5, lane = tid & 31;
    const int g = lane >> 2, tig = lane & 3;
    const int q = lane >> 3, rr = lane & 7;   // ldmatrix roles

    const uint32_t offB = ((((q >> 1) * 8 + rr) * SMRH) + (q & 1) * 8) * 2;
    const uint32_t offV2 = (((64 + rr) * SMRH) + (q & 1) * 8) * 2;

    const __half* Kg = g_K + (size_t)bh * SEQ * DHD;
    const __half* Vg = g_V + (size_t)bh * DHD * SEQ;   // [dh][seq]

    // prologue: tile 0 -> buf0 (commit group #0)
#pragma unroll
    for (int i = 0; i < 4; i++) {
        int idx = tid + i * 128;
        int r = idx >> 3, c8 = (idx & 7) << 3;
        cp16(sm_u32 + (r * SMRH + c8) * 2,        Kg + (size_t)r * DHD + c8);
        cp16(sm_u32 + (KSZ + r * SMRH + c8) * 2,  Vg + (size_t)r * SEQ + c8);
    }
    cp_commit();

    // stage Q [128 x 64] into buf1 region
    {
        const __half* Qg = g_Q + ((size_t)bh * SEQ + q0) * DHD;
        __half* stage = smh + BUFSZ;
#pragma unroll
        for (int i = 0; i < 8; i++) {
            int idx = tid + i * 128;
            int r = idx >> 3, c8 = (idx & 7) << 3;
            *(uint4*)&stage[r * SMRH + c8] = *(const uint4*)(Qg + (size_t)r * DHD + c8);
        }
    }
    __syncthreads();

    // Q fragments: warp wid owns rows wid*32 .. wid*32+31
    uint32_t qf[2][4][4];
    {
        const __half* stage = smh + BUFSZ;
        const int rbase = wid * 32;
#pragma unroll
        for (int t = 0; t < 2; t++)
#pragma unroll
            for (int kki = 0; kki < 4; kki++) {
                int kk = kki * 16;
                int r = rbase + t * 16 + g;
                qf[t][kki][0] = *(const uint32_t*)&stage[r * SMRH + kk + 2 * tig];
                qf[t][kki][1] = *(const uint32_t*)&stage[(r + 8) * SMRH + kk + 2 * tig];
                qf[t][kki][2] = *(const uint32_t*)&stage[r * SMRH + kk + 2 * tig + 8];
                qf[t][kki][3] = *(const uint32_t*)&stage[(r + 8) * SMRH + kk + 2 * tig + 8];
            }
    }
    __syncthreads();   // qf reads done before tile-1 cp.async overwrites buf1

    // tile 1 -> buf1 (commit group #1)
    {
        const __half* kp = Kg + (size_t)64 * DHD;
        const __half* vp = Vg + 64;
        const uint32_t kb = sm_u32 + BUFSZ * 2;
#pragma unroll
        for (int i = 0; i < 4; i++) {
            int idx = tid + i * 128;
            int r = idx >> 3, c8 = (idx & 7) << 3;
            cp16(kb + (r * SMRH + c8) * 2,        kp + (size_t)r * DHD + c8);
            cp16(kb + (KSZ + r * SMRH + c8) * 2,  vp + (size_t)r * SEQ + c8);
        }
        cp_commit();
    }

    // V^T rows 64..71 in ALL buffers: row 64 = 1.0 (row-sum col), 65..71 = 0
    for (int i = tid; i < NBUF * 8 * (SMRH / 2); i += 128) {
        int bi = i / (8 * (SMRH / 2));
        int r8 = (i / (SMRH / 2)) % 8;
        int cc = (i % (SMRH / 2)) * 2;
        __half v = (r8 == 0) ? __float2half(1.0f) : __float2half(0.0f);
        __half* dst = smh + bi * BUFSZ + KSZ + (64 + r8) * SMRH + cc;
        dst[0] = v; dst[1] = v;
    }

    float o[2][9][4] = {};   // nt=8 accumulates the row-sum (ones) column

    int p = 0;   // ring position of tile kt
    for (int kt = 0; kt < SEQ / 64; kt++) {
        cp_wait1();        // tile kt complete (tile kt+1 may be in flight)
        __syncthreads();   // all warps done with prior-iter reads of the prefetch target

        // prefetch tile kt+2 into buf (p+2)%3
        if (kt + 2 < SEQ / 64) {
            int p2 = p + 2; if (p2 >= NBUF) p2 -= NBUF;
            const uint32_t kb = sm_u32 + p2 * BUFSZ * 2;
            const __half* kp = Kg + (size_t)(kt + 2) * 64 * DHD;
            const __half* vp = Vg + (size_t)(kt + 2) * 64;
#pragma unroll
            for (int i = 0; i < 4; i++) {
                int idx = tid + i * 128;
                int r = idx >> 3, c8 = (idx & 7) << 3;
                cp16(kb + (r * SMRH + c8) * 2,        kp + (size_t)r * DHD + c8);
                cp16(kb + (KSZ + r * SMRH + c8) * 2,  vp + (size_t)r * SEQ + c8);
            }
        }
        cp_commit();

        const uint32_t ks_u32 = sm_u32 + p * BUFSZ * 2;        // [key][dh]
        const uint32_t vt_u32 = ks_u32 + KSZ * 2;              // [dh(+ones)][key]

        // ---- S = Q@K^T - SHIFT over nt pairs; P = exp2(S) packed to fp16 ----
        uint32_t pf[2][4][4];
#pragma unroll
        for (int j = 0; j < 4; j++) {          // nt pair (2j, 2j+1)
            float sA0[4] = {-SHIFT, -SHIFT, -SHIFT, -SHIFT};
            float sB0[4] = {-SHIFT, -SHIFT, -SHIFT, -SHIFT};
            float sA1[4] = {-SHIFT, -SHIFT, -SHIFT, -SHIFT};
            float sB1[4] = {-SHIFT, -SHIFT, -SHIFT, -SHIFT};
#pragma unroll
            for (int kki = 0; kki < 4; kki++) {
                uint32_t b00, b01, b10, b11;
                ldm4(b00, b01, b10, b11, ks_u32 + (j * 16 * SMRH + kki * 16) * 2 + offB);
                mma_f16(sA0, qf[0][kki][0], qf[0][kki][1], qf[0][kki][2], qf[0][kki][3], b00, b01);
                mma_f16(sB0, qf[1][kki][0], qf[1][kki][1], qf[1][kki][2], qf[1][kki][3], b00, b01);
                mma_f16(sA1, qf[0][kki][0], qf[0][kki][1], qf[0][kki][2], qf[0][kki][3], b10, b11);
                mma_f16(sB1, qf[1][kki][0], qf[1][kki][1], qf[1][kki][2], qf[1][kki][3], b10, b11);
            }
            pf[0][j][0] = hex2(h2(sA0[0], sA0[1]));
            pf[0][j][1] = hex2(h2(sA0[2], sA0[3]));
            pf[0][j][2] = hex2(h2(sA1[0], sA1[1]));
            pf[0][j][3] = hex2(h2(sA1[2], sA1[3]));
            pf[1][j][0] = hex2(h2(sB0[0], sB0[1]));
            pf[1][j][1] = hex2(h2(sB0[2], sB0[3]));
            pf[1][j][2] = hex2(h2(sB1[0], sB1[1]));
            pf[1][j][3] = hex2(h2(sB1[2], sB1[3]));
        }

        // ---- O += P @ [V | 1] (ldmatrix B loads) ----
#pragma unroll
        for (int kki = 0; kki < 4; kki++) {
#pragma unroll
            for (int j = 0; j < 4; j++) {
                uint32_t b00, b01, b10, b11;
                ldm4(b00, b01, b10, b11, vt_u32 + (j * 16 * SMRH + kki * 16) * 2 + offB);
                mma_f16(o[0][2 * j],     pf[0][kki][0], pf[0][kki][1], pf[0][kki][2], pf[0][kki][3], b00, b01);
                mma_f16(o[1][2 * j],     pf[1][kki][0], pf[1][kki][1], pf[1][kki][2], pf[1][kki][3], b00, b01);
                mma_f16(o[0][2 * j + 1], pf[0][kki][0], pf[0][kki][1], pf[0][kki][2], pf[0][kki][3], b10, b11);
                mma_f16(o[1][2 * j + 1], pf[1][kki][0], pf[1][kki][1], pf[1][kki][2], pf[1][kki][3], b10, b11);
            }
            {
                uint32_t b0, b1;
                ldm2(b0, b1, vt_u32 + (kki * 16) * 2 + offV2);
                mma_f16(o[0][8], pf[0][kki][0], pf[0][kki][1], pf[0][kki][2], pf[0][kki][3], b0, b1);
                mma_f16(o[1][8], pf[1][kki][0], pf[1][kki][1], pf[1][kki][2], pf[1][kki][3], b0, b1);
            }
        }

        if (++p == NBUF) p = 0;
    }

    // ---- epilogue: l from the ones column, normalize, store fp16 ----
    const int b = bh >> 3, h = bh & 7;
#pragma unroll
    for (int t = 0; t < 2; t++) {
        float l0 = __shfl_sync(0xffffffffu, o[t][8][0], lane & ~3);
        float l1 = __shfl_sync(0xffffffffu, o[t][8][2], lane & ~3);
        float inv0 = 1.0f / l0, inv1 = 1.0f / l1;
        int s0 = q0 + wid * 32 + t * 16 + g;
#pragma unroll
        for (int nt = 0; nt < 8; nt++) {
            int e = h * DHD + nt * 8 + 2 * tig;
            *(uint32_t*)&g_attn[((size_t)(b * SEQ + s0)) * EMB + e] =
                h2(o[t][nt][0] * inv0, o[t][nt][1] * inv0);
            *(uint32_t*)&g_attn[((size_t)(b * SEQ + s0 + 8)) * EMB + e] =
                h2(o[t][nt][2] * inv1, o[t][nt][3] * inv1);
        }
    }
}

// ---------------------------------------------------------------------------
// Kernel 3: out = attn @ Wo^T + bo. NEW: 128 threads = 4 warps x 16 rows,
// 64x128 tiles -> grid (B*S/64, EMB/128) = 512 CTAs, 4 CTAs/SM (single wave,
// 16 warps/SM). W fragments via ldmatrix. Double-buffered cp.async k-loop.
// ---------------------------------------------------------------------------
#define OPA_SZ (64*SMRH)
#define OPW_SZ (128*SMRH)
#define OP_BUF (OPA_SZ+OPW_SZ)
#define OUT_SMEM (2*OP_BUF*2)

__global__ __launch_bounds__(128, 4)
void outproj_kernel(const float* __restrict__ bo, float* __restrict__ out)
{
    extern __shared__ __half smh[];
    const uint32_t sm_u32 = (uint32_t)__cvta_generic_to_shared(smh);

    const int m0b = blockIdx.x * 64, n0 = blockIdx.y * 128;
    const int tid = threadIdx.x;
    const int wid = tid >> 5, lane = tid & 31;
    const int g = lane >> 2, tig = lane & 3;
    const int q = lane >> 3, rr = lane & 7;
    const uint32_t offB = ((((q >> 1) * 8 + rr) * SMRH) + (q & 1) * 8) * 2;

    // prologue: chunk 0 -> buffer 0
#pragma unroll
    for (int i = 0; i < 4; i++) {
        int idx = tid + i * 128;
        int r = idx >> 3, c8 = (idx & 7) << 3;
        cp16(sm_u32 + (r * SMRH + c8) * 2, g_attn + (size_t)(m0b + r) * EMB + c8);
    }
#pragma unroll
    for (int i = 0; i < 8; i++) {
        int idx = tid + i * 128;
        int r = idx >> 3, c8 = (idx & 7) << 3;
        cp16(sm_u32 + (OPA_SZ + r * SMRH + c8) * 2, g_Wo_h + (size_t)(n0 + r) * EMB + c8);
    }
    cp_commit();

    float acc[16][4] = {};

    for (int ch = 0; ch < EMB / 64; ch++) {
        const int p = ch & 1;
        if (ch + 1 < EMB / 64) {
            const int k1 = (ch + 1) * 64;
            const uint32_t kb = sm_u32 + (p ^ 1) * OP_BUF * 2;
#pragma unroll
            for (int i = 0; i < 4; i++) {
                int idx = tid + i * 128;
                int r = idx >> 3, c8 = (idx & 7) << 3;
                cp16(kb + (r * SMRH + c8) * 2, g_attn + (size_t)(m0b + r) * EMB + k1 + c8);
            }
#pragma unroll
            for (int i = 0; i < 8; i++) {
                int idx = tid + i * 128;
                int r = idx >> 3, c8 = (idx & 7) << 3;
                cp16(kb + (OPA_SZ + r * SMRH + c8) * 2, g_Wo_h + (size_t)(n0 + r) * EMB + k1 + c8);
            }
        }
        cp_commit();
        cp_wait1();
        __syncthreads();

        const __half* As = smh + p * OP_BUF;
        const uint32_t ws_u32 = sm_u32 + (p * OP_BUF + OPA_SZ) * 2;
        const int r = wid * 16 + g;

#pragma unroll
        for (int kki = 0; kki < 4; kki++) {
            int kk = kki * 16;
            uint32_t a0 = *(const uint32_t*)&As[r * SMRH + kk + 2 * tig];
            uint32_t a1 = *(const uint32_t*)&As[(r + 8) * SMRH + kk + 2 * tig];
            uint32_t a2 = *(const uint32_t*)&As[r * SMRH + kk + 2 * tig + 8];
            uint32_t a3 = *(const uint32_t*)&As[(r + 8) * SMRH + kk + 2 * tig + 8];
#pragma unroll
            for (int j = 0; j < 8; j++) {     // n-row pair (16j .. 16j+15)
                uint32_t b00, b01, b10, b11;
                ldm4(b00, b01, b10, b11, ws_u32 + (j * 16 * SMRH + kk) * 2 + offB);
                mma_f16(acc[2 * j],     a0, a1, a2, a3, b00, b01);
                mma_f16(acc[2 * j + 1], a0, a1, a2, a3, b10, b11);
            }
        }
        __syncthreads();
    }

    {
        int row = m0b + wid * 16 + g;
#pragma unroll
        for (int nt = 0; nt < 16; nt++) {
            int col = n0 + nt * 8 + 2 * tig;
            float2 bias = *(const float2*)&bo[col];
            float2 v0, v1;
            v0.x = acc[nt][0] + bias.x; v0.y = acc[nt][1] + bias.y;
            v1.x = acc[nt][2] + bias.x; v1.y = acc[nt][3] + bias.y;
            *(float2*)&out[(size_t)row * EMB + col]       = v0;
            *(float2*)&out[(size_t)(row + 8) * EMB + col] = v1;
        }
    }
}

// ---------------------------------------------------------------------------
extern "C" void kernel_launch(void* const* d_in, const int* in_sizes, int n_in,
                              void* d_out, int out_size)
{
    const float* x  = (const float*)d_in[0];
    const float* Wq = (const float*)d_in[1];
    const float* bq = (const float*)d_in[2];
    const float* Wk = (const float*)d_in[3];
    const float* bk = (const float*)d_in[4];
    const float* Wv = (const float*)d_in[5];
    const float* bv = (const float*)d_in[6];
    const float* Wo = (const float*)d_in[7];
    const float* bo = (const float*)d_in[8];
    float* out = (float*)d_out;

    cudaFuncSetAttribute(qkv_conv_kernel, cudaFuncAttributeMaxDynamicSharedMemorySize, QKV_SMEM);
    cudaFuncSetAttribute(attn_kernel,     cudaFuncAttributeMaxDynamicSharedMemorySize, ATTN_SMEM);
    cudaFuncSetAttribute(outproj_kernel,  cudaFuncAttributeMaxDynamicSharedMemorySize, OUT_SMEM);

    qkv_conv_kernel<<<768, 256, QKV_SMEM>>>(x, Wq, bq, Wk, bk, Wv, bv, Wo);
    attn_kernel<<<dim3(SEQ / 128, BH), 128, ATTN_SMEM>>>();
    outproj_kernel<<<dim3((BATCH * SEQ) / 64, EMB / 128), 128, OUT_SMEM>>>(bo, out);
}

// round 17
// speedup vs baseline: 1.0184x; 1.0184x over previous
#include <cuda_runtime.h>
#include <cuda_fp16.h>
#include <math.h>
#include <stdint.h>

#define BATCH 4
#define SEQ   2048
#define EMB   512
#define NH    8
#define DHD   64
#define BH    (BATCH*NH)

#define SMRH  72                // smem row stride in halves
#define LOG2E 1.4426950408889634f
#define SHIFT 8.0f              // fixed softmax shift (exp2 domain)

// Scratch (fp16). V stored transposed: [bh][dh][seq].
__device__ __align__(16) __half g_Q[BH * SEQ * DHD];
__device__ __align__(16) __half g_K[BH * SEQ * DHD];
__device__ __align__(16) __half g_V[BH * DHD * SEQ];
__device__ __align__(16) __half g_attn[BATCH * SEQ * EMB];
__device__ __align__(16) __half g_Wo_h[EMB * EMB];

// ---- helpers --------------------------------------------------------------
__device__ __forceinline__ uint32_t h2(float a, float b) {
    __half2 h = __floats2half2_rn(a, b);
    return *(uint32_t*)&h;
}
__device__ __forceinline__ uint32_t hex2(uint32_t x) {   // exp2 on packed fp16 pair
    uint32_t y;
    asm("ex2.approx.f16x2 %0, %1;" : "=r"(y) : "r"(x));
    return y;
}
__device__ __forceinline__ void mma_f16(float c[4],
                                        uint32_t a0, uint32_t a1, uint32_t a2, uint32_t a3,
                                        uint32_t b0, uint32_t b1) {
    asm volatile(
        "mma.sync.aligned.m16n8k16.row.col.f32.f16.f16.f32 "
        "{%0,%1,%2,%3}, {%4,%5,%6,%7}, {%8,%9}, {%0,%1,%2,%3};"
        : "+f"(c[0]), "+f"(c[1]), "+f"(c[2]), "+f"(c[3])
        : "r"(a0), "r"(a1), "r"(a2), "r"(a3), "r"(b0), "r"(b1));
}
__device__ __forceinline__ void ldm4(uint32_t& r0, uint32_t& r1, uint32_t& r2, uint32_t& r3,
                                     uint32_t addr) {
    asm volatile("ldmatrix.sync.aligned.m8n8.x4.shared.b16 {%0,%1,%2,%3}, [%4];"
                 : "=r"(r0), "=r"(r1), "=r"(r2), "=r"(r3) : "r"(addr));
}
__device__ __forceinline__ void ldm2(uint32_t& r0, uint32_t& r1, uint32_t addr) {
    asm volatile("ldmatrix.sync.aligned.m8n8.x2.shared.b16 {%0,%1}, [%2];"
                 : "=r"(r0), "=r"(r1) : "r"(addr));
}
__device__ __forceinline__ void cp16(uint32_t dst, const void* src) {
    asm volatile("cp.async.cg.shared.global [%0], [%1], 16;" :: "r"(dst), "l"(src));
}
__device__ __forceinline__ void cp_commit() { asm volatile("cp.async.commit_group;"); }
__device__ __forceinline__ void cp_wait1()  { asm volatile("cp.async.wait_group 1;" ::: "memory"); }

// ---------------------------------------------------------------------------
// Kernel 1: fused QKV projection + Wo fp32->fp16 conversion (proven, 20.6us).
// ---------------------------------------------------------------------------
#define QKV_BUFH (64*SMRH)
#define QKV_SMEM ((128*SMRH + 3*QKV_BUFH) * 2)
#define TSR 136                  // transpose-stage stride in halves

__global__ __launch_bounds__(256)
void qkv_conv_kernel(const float* __restrict__ x,
                     const float* __restrict__ Wq, const float* __restrict__ bq,
                     const float* __restrict__ Wk, const float* __restrict__ bk,
                     const float* __restrict__ Wv, const float* __restrict__ bv,
                     const float* __restrict__ Wo)
{
    if (blockIdx.x >= 512) {
        int idx = (blockIdx.x - 512) * 256 + threadIdx.x;
        float4 v = *(const float4*)(Wo + (size_t)idx * 4);
        uint2 o;
        o.x = h2(v.x, v.y);
        o.y = h2(v.z, v.w);
        *(uint2*)&g_Wo_h[(size_t)idx * 4] = o;
        return;
    }

    extern __shared__ __half smh[];
    __half* Xs = smh;                    // [128][SMRH]
    __half* Wsb = smh + 128 * SMRH;      // 3 x [64][SMRH]

    const int bid = blockIdx.x;
    const int st = bid & 15, b = (bid >> 4) & 3, h = bid >> 6;
    const int tid = threadIdx.x;
    const int wid = tid >> 5, lane = tid & 31;
    const int g = lane >> 2, tig = lane & 3;

    const float* xb = x + ((size_t)(b * SEQ + st * 128)) * EMB + h * DHD;
#pragma unroll
    for (int i = 0; i < 8; i++) {
        int idx = tid + i * 256;
        int r = idx >> 4, c4 = (idx & 15) << 2;
        float4 v = *(const float4*)(xb + (size_t)r * EMB + c4);
        uint2 o; o.x = h2(v.x, v.y); o.y = h2(v.z, v.w);
        *(uint2*)&Xs[r * SMRH + c4] = o;
    }
    const float* Wm[3] = {Wq, Wk, Wv};
#pragma unroll
    for (int m = 0; m < 3; m++) {
        const float* wsrc = Wm[m] + h * DHD * DHD;
        __half* Ws = Wsb + m * QKV_BUFH;
#pragma unroll
        for (int i = 0; i < 4; i++) {
            int idx = tid + i * 256;
            int r = idx >> 4, c4 = (idx & 15) << 2;
            float4 v = *(const float4*)(wsrc + r * DHD + c4);
            uint2 o; o.x = h2(v.x, v.y); o.y = h2(v.z, v.w);
            *(uint2*)&Ws[r * SMRH + c4] = o;
        }
    }
    __syncthreads();

    uint32_t xf[4][4];
    {
        const int r0 = wid * 16 + g;
#pragma unroll
        for (int kki = 0; kki < 4; kki++) {
            int kk = kki * 16;
            xf[kki][0] = *(const uint32_t*)&Xs[r0 * SMRH + kk + 2 * tig];
            xf[kki][1] = *(const uint32_t*)&Xs[(r0 + 8) * SMRH + kk + 2 * tig];
            xf[kki][2] = *(const uint32_t*)&Xs[r0 * SMRH + kk + 2 * tig + 8];
            xf[kki][3] = *(const uint32_t*)&Xs[(r0 + 8) * SMRH + kk + 2 * tig + 8];
        }
    }

    const float* bm[3] = {bq, bk, bv};
    const int bh = b * NH + h;
    const int row = wid * 16 + g;

#pragma unroll
    for (int m = 0; m < 3; m++) {
        const __half* Ws = Wsb + m * QKV_BUFH;
        float acc[8][4] = {};
#pragma unroll
        for (int kki = 0; kki < 4; kki++) {
            int kk = kki * 16;
#pragma unroll
            for (int nt = 0; nt < 8; nt++) {
                uint32_t b0 = *(const uint32_t*)&Ws[(nt * 8 + g) * SMRH + kk + 2 * tig];
                uint32_t b1 = *(const uint32_t*)&Ws[(nt * 8 + g) * SMRH + kk + 2 * tig + 8];
                mma_f16(acc[nt], xf[kki][0], xf[kki][1], xf[kki][2], xf[kki][3], b0, b1);
            }
        }
        const float* bb = bm[m] + h * DHD;
        if (m < 2) {
            const float scale = (m == 0) ? 0.125f * LOG2E : 1.0f;
            __half* op = ((m == 0) ? g_Q : g_K) + ((size_t)bh * SEQ + st * 128) * DHD;
#pragma unroll
            for (int nt = 0; nt < 8; nt++) {
                int col = nt * 8 + 2 * tig;
                float2 bias = *(const float2*)&bb[col];
                *(uint32_t*)&op[(size_t)row * DHD + col] =
                    h2((acc[nt][0] + bias.x) * scale, (acc[nt][1] + bias.y) * scale);
                *(uint32_t*)&op[(size_t)(row + 8) * DHD + col] =
                    h2((acc[nt][2] + bias.x) * scale, (acc[nt][3] + bias.y) * scale);
            }
        } else {
            // V: stage transpose [64 dh][128 seq] in smem, then coalesced uint4 STG
            __syncthreads();
            __half* Ts = smh;
#pragma unroll
            for (int nt = 0; nt < 8; nt++) {
                int col = nt * 8 + 2 * tig;
                float2 bias = *(const float2*)&bb[col];
                Ts[col * TSR + row]           = __float2half(acc[nt][0] + bias.x);
                Ts[(col + 1) * TSR + row]     = __float2half(acc[nt][1] + bias.y);
                Ts[col * TSR + row + 8]       = __float2half(acc[nt][2] + bias.x);
                Ts[(col + 1) * TSR + row + 8] = __float2half(acc[nt][3] + bias.y);
            }
            __syncthreads();
            __half* op = g_V + (size_t)bh * DHD * SEQ + st * 128;
#pragma unroll
            for (int i = 0; i < 4; i++) {
                int idx = tid + i * 256;
                int r = idx >> 4, c8 = (idx & 15) * 8;
                *(uint4*)(op + (size_t)r * SEQ + c8) = *(const uint4*)&Ts[r * TSR + c8];
            }
        }
    }
}

// ---------------------------------------------------------------------------
// Kernel 2: flash attention (round-14 proven best) + PDL early launch.
// Independent prologue (ones-row init) runs before griddepsync.
// grid (SEQ/128, BH), 128 threads.
// ---------------------------------------------------------------------------
#define KSZ   (64*SMRH)
#define VSZ   (72*SMRH)
#define BUFSZ (KSZ+VSZ)
#define NBUF  3
#define ATTN_SMEM (NBUF*BUFSZ*2)

__global__ __launch_bounds__(128, 3)
void attn_kernel()
{
    extern __shared__ __half smh[];
    const uint32_t sm_u32 = (uint32_t)__cvta_generic_to_shared(smh);

    const int bh = blockIdx.y;
    const int q0 = blockIdx.x * 128;
    const int tid = threadIdx.x;
    const int wid = tid >> 5, lane = tid & 31;
    const int g = lane >> 2, tig = lane & 3;
    const int q = lane >> 3, rr = lane & 7;   // ldmatrix roles

    const uint32_t offB = ((((q >> 1) * 8 + rr) * SMRH) + (q & 1) * 8) * 2;
    const uint32_t offV2 = (((64 + rr) * SMRH) + (q & 1) * 8) * 2;

    // ---- upstream-independent prologue: ones rows in ALL ring buffers ----
    for (int i = tid; i < NBUF * 8 * (SMRH / 2); i += 128) {
        int bi = i / (8 * (SMRH / 2));
        int r8 = (i / (SMRH / 2)) % 8;
        int cc = (i % (SMRH / 2)) * 2;
        __half v = (r8 == 0) ? __float2half(1.0f) : __float2half(0.0f);
        __half* dst = smh + bi * BUFSZ + KSZ + (64 + r8) * SMRH + cc;
        dst[0] = v; dst[1] = v;
    }

    // wait for qkv_conv grid to finish producing g_Q/g_K/g_V
    cudaGridDependencySynchronize();

    const __half* Kg = g_K + (size_t)bh * SEQ * DHD;
    const __half* Vg = g_V + (size_t)bh * DHD * SEQ;   // [dh][seq]

    // prologue: tile 0 -> buf0 (commit group #0)
#pragma unroll
    for (int i = 0; i < 4; i++) {
        int idx = tid + i * 128;
        int r = idx >> 3, c8 = (idx & 7) << 3;
        cp16(sm_u32 + (r * SMRH + c8) * 2,        Kg + (size_t)r * DHD + c8);
        cp16(sm_u32 + (KSZ + r * SMRH + c8) * 2,  Vg + (size_t)r * SEQ + c8);
    }
    cp_commit();

    // stage Q [128 x 64] into buf1 region
    {
        const __half* Qg = g_Q + ((size_t)bh * SEQ + q0) * DHD;
        __half* stage = smh + BUFSZ;
#pragma unroll
        for (int i = 0; i < 8; i++) {
            int idx = tid + i * 128;
            int r = idx >> 3, c8 = (idx & 7) << 3;
            *(uint4*)&stage[r * SMRH + c8] = *(const uint4*)(Qg + (size_t)r * DHD + c8);
        }
    }
    __syncthreads();

    // Q fragments: warp wid owns rows wid*32 .. wid*32+31
    uint32_t qf[2][4][4];
    {
        const __half* stage = smh + BUFSZ;
        const int rbase = wid * 32;
#pragma unroll
        for (int t = 0; t < 2; t++)
#pragma unroll
            for (int kki = 0; kki < 4; kki++) {
                int kk = kki * 16;
                int r = rbase + t * 16 + g;
                qf[t][kki][0] = *(const uint32_t*)&stage[r * SMRH + kk + 2 * tig];
                qf[t][kki][1] = *(const uint32_t*)&stage[(r + 8) * SMRH + kk + 2 * tig];
                qf[t][kki][2] = *(const uint32_t*)&stage[r * SMRH + kk + 2 * tig + 8];
                qf[t][kki][3] = *(const uint32_t*)&stage[(r + 8) * SMRH + kk + 2 * tig + 8];
            }
    }
    __syncthreads();   // qf reads done before tile-1 cp.async overwrites buf1

    // tile 1 -> buf1 (commit group #1)
    {
        const __half* kp = Kg + (size_t)64 * DHD;
        const __half* vp = Vg + 64;
        const uint32_t kb = sm_u32 + BUFSZ * 2;
#pragma unroll
        for (int i = 0; i < 4; i++) {
            int idx = tid + i * 128;
            int r = idx >> 3, c8 = (idx & 7) << 3;
            cp16(kb + (r * SMRH + c8) * 2,        kp + (size_t)r * DHD + c8);
            cp16(kb + (KSZ + r * SMRH + c8) * 2,  vp + (size_t)r * SEQ + c8);
        }
        cp_commit();
    }

    float o[2][9][4] = {};   // nt=8 accumulates the row-sum (ones) column

    int p = 0;   // ring position of tile kt
    for (int kt = 0; kt < SEQ / 64; kt++) {
        cp_wait1();        // tile kt complete (tile kt+1 may be in flight)
        __syncthreads();   // all warps done with prior-iter reads of the prefetch target

        // prefetch tile kt+2 into buf (p+2)%3
        if (kt + 2 < SEQ / 64) {
            int p2 = p + 2; if (p2 >= NBUF) p2 -= NBUF;
            const uint32_t kb = sm_u32 + p2 * BUFSZ * 2;
            const __half* kp = Kg + (size_t)(kt + 2) * 64 * DHD;
            const __half* vp = Vg + (size_t)(kt + 2) * 64;
#pragma unroll
            for (int i = 0; i < 4; i++) {
                int idx = tid + i * 128;
                int r = idx >> 3, c8 = (idx & 7) << 3;
                cp16(kb + (r * SMRH + c8) * 2,        kp + (size_t)r * DHD + c8);
                cp16(kb + (KSZ + r * SMRH + c8) * 2,  vp + (size_t)r * SEQ + c8);
            }
        }
        cp_commit();

        const uint32_t ks_u32 = sm_u32 + p * BUFSZ * 2;        // [key][dh]
        const uint32_t vt_u32 = ks_u32 + KSZ * 2;              // [dh(+ones)][key]

        // ---- S = Q@K^T - SHIFT over nt pairs; P = exp2(S) packed to fp16 ----
        uint32_t pf[2][4][4];
#pragma unroll
        for (int j = 0; j < 4; j++) {          // nt pair (2j, 2j+1)
            float sA0[4] = {-SHIFT, -SHIFT, -SHIFT, -SHIFT};
            float sB0[4] = {-SHIFT, -SHIFT, -SHIFT, -SHIFT};
            float sA1[4] = {-SHIFT, -SHIFT, -SHIFT, -SHIFT};
            float sB1[4] = {-SHIFT, -SHIFT, -SHIFT, -SHIFT};
#pragma unroll
            for (int kki = 0; kki < 4; kki++) {
                uint32_t b00, b01, b10, b11;
                ldm4(b00, b01, b10, b11, ks_u32 + (j * 16 * SMRH + kki * 16) * 2 + offB);
                mma_f16(sA0, qf[0][kki][0], qf[0][kki][1], qf[0][kki][2], qf[0][kki][3], b00, b01);
                mma_f16(sB0, qf[1][kki][0], qf[1][kki][1], qf[1][kki][2], qf[1][kki][3], b00, b01);
                mma_f16(sA1, qf[0][kki][0], qf[0][kki][1], qf[0][kki][2], qf[0][kki][3], b10, b11);
                mma_f16(sB1, qf[1][kki][0], qf[1][kki][1], qf[1][kki][2], qf[1][kki][3], b10, b11);
            }
            pf[0][j][0] = hex2(h2(sA0[0], sA0[1]));
            pf[0][j][1] = hex2(h2(sA0[2], sA0[3]));
            pf[0][j][2] = hex2(h2(sA1[0], sA1[1]));
            pf[0][j][3] = hex2(h2(sA1[2], sA1[3]));
            pf[1][j][0] = hex2(h2(sB0[0], sB0[1]));
            pf[1][j][1] = hex2(h2(sB0[2], sB0[3]));
            pf[1][j][2] = hex2(h2(sB1[0], sB1[1]));
            pf[1][j][3] = hex2(h2(sB1[2], sB1[3]));
        }

        // ---- O += P @ [V | 1] (ldmatrix B loads) ----
#pragma unroll
        for (int kki = 0; kki < 4; kki++) {
#pragma unroll
            for (int j = 0; j < 4; j++) {
                uint32_t b00, b01, b10, b11;
                ldm4(b00, b01, b10, b11, vt_u32 + (j * 16 * SMRH + kki * 16) * 2 + offB);
                mma_f16(o[0][2 * j],     pf[0][kki][0], pf[0][kki][1], pf[0][kki][2], pf[0][kki][3], b00, b01);
                mma_f16(o[1][2 * j],     pf[1][kki][0], pf[1][kki][1], pf[1][kki][2], pf[1][kki][3], b00, b01);
                mma_f16(o[0][2 * j + 1], pf[0][kki][0], pf[0][kki][1], pf[0][kki][2], pf[0][kki][3], b10, b11);
                mma_f16(o[1][2 * j + 1], pf[1][kki][0], pf[1][kki][1], pf[1][kki][2], pf[1][kki][3], b10, b11);
            }
            {
                uint32_t b0, b1;
                ldm2(b0, b1, vt_u32 + (kki * 16) * 2 + offV2);
                mma_f16(o[0][8], pf[0][kki][0], pf[0][kki][1], pf[0][kki][2], pf[0][kki][3], b0, b1);
                mma_f16(o[1][8], pf[1][kki][0], pf[1][kki][1], pf[1][kki][2], pf[1][kki][3], b0, b1);
            }
        }

        if (++p == NBUF) p = 0;
    }

    // ---- epilogue: l from the ones column, normalize, store fp16 ----
    const int b = bh >> 3, h = bh & 7;
#pragma unroll
    for (int t = 0; t < 2; t++) {
        float l0 = __shfl_sync(0xffffffffu, o[t][8][0], lane & ~3);
        float l1 = __shfl_sync(0xffffffffu, o[t][8][2], lane & ~3);
        float inv0 = 1.0f / l0, inv1 = 1.0f / l1;
        int s0 = q0 + wid * 32 + t * 16 + g;
#pragma unroll
        for (int nt = 0; nt < 8; nt++) {
            int e = h * DHD + nt * 8 + 2 * tig;
            *(uint32_t*)&g_attn[((size_t)(b * SEQ + s0)) * EMB + e] =
                h2(o[t][nt][0] * inv0, o[t][nt][1] * inv0);
            *(uint32_t*)&g_attn[((size_t)(b * SEQ + s0 + 8)) * EMB + e] =
                h2(o[t][nt][2] * inv1, o[t][nt][3] * inv1);
        }
    }
}

// ---------------------------------------------------------------------------
// Kernel 3: out = attn @ Wo^T + bo (round-14 proven 128x128 double-buffer)
// + PDL early launch. grid (B*S/128, EMB/128), 256 threads.
// ---------------------------------------------------------------------------
#define OP_ASZ (128*SMRH)
#define OP_WSZ (128*SMRH)
#define OP_BUF (OP_ASZ+OP_WSZ)
#define OUT_SMEM (2*OP_BUF*2)

__global__ __launch_bounds__(256)
void outproj_kernel(const float* __restrict__ bo, float* __restrict__ out)
{
    extern __shared__ __half smh[];
    const uint32_t sm_u32 = (uint32_t)__cvta_generic_to_shared(smh);

    const int m0b = blockIdx.x * 128, n0 = blockIdx.y * 128;
    const int tid = threadIdx.x;
    const int wid = tid >> 5, lane = tid & 31;
    const int g = lane >> 2, tig = lane & 3;
    const int wm = wid & 3, wn = wid >> 2;
    const int rbase = wm * 32;

    // wait for attn grid to finish producing g_attn
    cudaGridDependencySynchronize();

    // prologue: chunk 0 -> buffer 0
#pragma unroll
    for (int i = 0; i < 4; i++) {
        int idx = tid + i * 256;
        int r = idx >> 3, c8 = (idx & 7) << 3;
        cp16(sm_u32 + (r * SMRH + c8) * 2, g_attn + (size_t)(m0b + r) * EMB + c8);
        cp16(sm_u32 + (OP_ASZ + r * SMRH + c8) * 2, g_Wo_h + (size_t)(n0 + r) * EMB + c8);
    }
    cp_commit();

    float acc[2][8][4] = {};

    for (int ch = 0; ch < EMB / 64; ch++) {
        const int p = ch & 1;
        if (ch + 1 < EMB / 64) {
            const int k1 = (ch + 1) * 64;
            const uint32_t kb = sm_u32 + (p ^ 1) * OP_BUF * 2;
#pragma unroll
            for (int i = 0; i < 4; i++) {
                int idx = tid + i * 256;
                int r = idx >> 3, c8 = (idx & 7) << 3;
                cp16(kb + (r * SMRH + c8) * 2, g_attn + (size_t)(m0b + r) * EMB + k1 + c8);
                cp16(kb + (OP_ASZ + r * SMRH + c8) * 2, g_Wo_h + (size_t)(n0 + r) * EMB + k1 + c8);
            }
        }
        cp_commit();
        cp_wait1();
        __syncthreads();

        const __half* As = smh + p * OP_BUF;
        const __half* Ws = smh + p * OP_BUF + OP_ASZ;

#pragma unroll
        for (int kki = 0; kki < 4; kki++) {
            int kk = kki * 16;
            uint32_t a[2][4];
#pragma unroll
            for (int t = 0; t < 2; t++) {
                int r = rbase + t * 16 + g;
                a[t][0] = *(const uint32_t*)&As[r * SMRH + kk + 2 * tig];
                a[t][1] = *(const uint32_t*)&As[(r + 8) * SMRH + kk + 2 * tig];
                a[t][2] = *(const uint32_t*)&As[r * SMRH + kk + 2 * tig + 8];
                a[t][3] = *(const uint32_t*)&As[(r + 8) * SMRH + kk + 2 * tig + 8];
            }
#pragma unroll
            for (int nt = 0; nt < 8; nt++) {
                int wr = wn * 64 + nt * 8 + g;
                uint32_t b0 = *(const uint32_t*)&Ws[wr * SMRH + kk + 2 * tig];
                uint32_t b1 = *(const uint32_t*)&Ws[wr * SMRH + kk + 2 * tig + 8];
                mma_f16(acc[0][nt], a[0][0], a[0][1], a[0][2], a[0][3], b0, b1);
                mma_f16(acc[1][nt], a[1][0], a[1][1], a[1][2], a[1][3], b0, b1);
            }
        }
        __syncthreads();
    }

#pragma unroll
    for (int t = 0; t < 2; t++) {
        int row = m0b + wm * 32 + t * 16 + g;
#pragma unroll
        for (int nt = 0; nt < 8; nt++) {
            int col = n0 + wn * 64 + nt * 8 + 2 * tig;
            float2 bias = *(const float2*)&bo[col];
            float2 v0, v1;
            v0.x = acc[t][nt][0] + bias.x; v0.y = acc[t][nt][1] + bias.y;
            v1.x = acc[t][nt][2] + bias.x; v1.y = acc[t][nt][3] + bias.y;
            *(float2*)&out[(size_t)row * EMB + col]       = v0;
            *(float2*)&out[(size_t)(row + 8) * EMB + col] = v1;
        }
    }
}

// ---------------------------------------------------------------------------
extern "C" void kernel_launch(void* const* d_in, const int* in_sizes, int n_in,
                              void* d_out, int out_size)
{
    const float* x  = (const float*)d_in[0];
    const float* Wq = (const float*)d_in[1];
    const float* bq = (const float*)d_in[2];
    const float* Wk = (const float*)d_in[3];
    const float* bk = (const float*)d_in[4];
    const float* Wv = (const float*)d_in[5];
    const float* bv = (const float*)d_in[6];
    const float* Wo = (const float*)d_in[7];
    const float* bo = (const float*)d_in[8];
    float* out = (float*)d_out;

    cudaFuncSetAttribute(qkv_conv_kernel, cudaFuncAttributeMaxDynamicSharedMemorySize, QKV_SMEM);
    cudaFuncSetAttribute(attn_kernel,     cudaFuncAttributeMaxDynamicSharedMemorySize, ATTN_SMEM);
    cudaFuncSetAttribute(outproj_kernel,  cudaFuncAttributeMaxDynamicSharedMemorySize, OUT_SMEM);

    qkv_conv_kernel<<<768, 256, QKV_SMEM>>>(x, Wq, bq, Wk, bk, Wv, bv, Wo);

    // attn: PDL early launch (waits on qkv via griddepsync in-kernel)
    {
        cudaLaunchAttribute attrs[1];
        attrs[0].id = cudaLaunchAttributeProgrammaticStreamSerialization;
        attrs[0].val.programmaticStreamSerializationAllowed = 1;
        cudaLaunchConfig_t cfg = {};
        cfg.gridDim = dim3(SEQ / 128, BH);
        cfg.blockDim = dim3(128);
        cfg.dynamicSmemBytes = ATTN_SMEM;
        cfg.stream = 0;
        cfg.attrs = attrs;
        cfg.numAttrs = 1;
        cudaLaunchKernelEx(&cfg, attn_kernel);
    }

    // outproj: PDL early launch (waits on attn via griddepsync in-kernel)
    {
        cudaLaunchAttribute attrs[1];
        attrs[0].id = cudaLaunchAttributeProgrammaticStreamSerialization;
        attrs[0].val.programmaticStreamSerializationAllowed = 1;
        cudaLaunchConfig_t cfg = {};
        cfg.gridDim = dim3((BATCH * SEQ) / 128, EMB / 128);
        cfg.blockDim = dim3(256);
        cfg.dynamicSmemBytes = OUT_SMEM;
        cfg.stream = 0;
        cfg.attrs = attrs;
        cfg.numAttrs = 1;
        cudaLaunchKernelEx(&cfg, outproj_kernel, bo, out);
    }
}